// round 15
// baseline (speedup 1.0000x reference)
#include <cuda_runtime.h>
#include <cuda_fp16.h>
#include <cstdint>

#define NR 16384
#define A16OFF 0            // 128 rows x 80B (32 fp16 + 16B pad)
#define B16OFF 10240        // 128 rows x 80B
#define STG    20480        // per-stage bytes; 4 stages = 80 KB

__device__ __half g_Th[(size_t)128 * NR];   // Tt[j][r] = fp16((X@W)[r][j]), K-major
__device__ float  g_H[(size_t)NR * 128];
__device__ float  g_ps[128 * 128], g_pq[128 * 128];
__device__ float  g_mean[128], g_scale[128], g_beta2[128];

__device__ __forceinline__ uint32_t s2u(const void* p) {
    uint32_t a;
    asm("{ .reg .u64 t; cvta.to.shared.u64 t, %1; cvt.u32.u64 %0, t; }" : "=r"(a) : "l"(p));
    return a;
}
#define LDSM4(r0, r1, r2, r3, addr) \
    asm volatile("ldmatrix.sync.aligned.m8n8.x4.shared.b16 {%0,%1,%2,%3}, [%4];" \
                 : "=r"(r0), "=r"(r1), "=r"(r2), "=r"(r3) : "r"(addr))

// ---------------- k1: Tt = fp16((X @ W)^T) ----------------
__global__ void k_xw(const float* __restrict__ X, const float* __restrict__ W) {
    extern __shared__ float sm[];
    float* ws = sm;              // [128*128] W
    float* xs = sm + 16384;      // [128]
    float* tl = sm + 16512;      // [128*33]
    int j = threadIdx.x;
    for (int i = j; i < 16384; i += 128) ws[i] = W[i];
    int r0 = blockIdx.x * 32;
    __syncthreads();
    for (int rr = 0; rr < 32; rr++) {
        xs[j] = X[(size_t)(r0 + rr) * 128 + j];
        __syncthreads();
        float acc = 0.f;
        #pragma unroll 16
        for (int k = 0; k < 128; k++) acc += xs[k] * ws[k * 128 + j];
        tl[j * 33 + rr] = acc;
        __syncthreads();
    }
    for (int idx = j; idx < 4096; idx += 128) {
        int jj = idx >> 5, r2 = idx & 31;
        g_Th[(size_t)jj * NR + r0 + r2] = __float2half_rn(tl[jj * 33 + r2]);
    }
}

// ---------------- k2: H = A @ T; LDG-A->fp16 STS; fp16 mma.sync ----------------
__global__ void __launch_bounds__(512, 1) k_gemm(const float* __restrict__ A) {
    extern __shared__ __align__(16) char smc[];
    const int tid = threadIdx.x, wid = tid >> 5, lid = tid & 31;
    const int gid = lid >> 2, tig = lid & 3;
    const int m0 = blockIdx.x * 128;
    const int wm = (wid & 3) * 32;          // warps 4(M) x 4(N), tile 32x32
    const int wn = (wid >> 2) * 32;
    const uint32_t smb = s2u(smc);

    const uint32_t aoff = A16OFF + (uint32_t)(wm + (lid & 15)) * 80u + ((lid >> 4) * 16u);
    const uint32_t boff = B16OFF + (uint32_t)(wn + ((lid & 16) >> 1) + (lid & 7)) * 80u
                        + ((lid & 8) ? 16u : 0u);

    // B: 512 x 16B segs, one cp.async per thread
    const int bn = tid >> 2, bs = tid & 3;
    auto loadB = [&](int ch, int st) {
        uint32_t dst = smb + (uint32_t)st * STG + B16OFF + bn * 80 + bs * 16;
        const __half* gp = g_Th + (size_t)bn * NR + (size_t)ch * 32 + bs * 8;
        asm volatile("cp.async.cg.shared.global [%0], [%1], 16;" :: "r"(dst), "l"(gp));
        asm volatile("cp.async.commit_group;" ::: "memory");
    };
    // A: 1024 x 16B segs, two LDG.128 per thread
    const int r0a = tid >> 3,        s0a = tid & 7;        // u = tid
    const int r1a = (tid + 512) >> 3, s1a = tid & 7;       // u = tid + 512
    auto ldgA = [&](int ch, float4* r) {
        r[0] = *(const float4*)(A + (size_t)(m0 + r0a) * NR + (size_t)ch * 32 + s0a * 4);
        r[1] = *(const float4*)(A + (size_t)(m0 + r1a) * NR + (size_t)ch * 32 + s1a * 4);
    };
    auto cvtsts = [&](int st, const float4* r) {
        char* base = smc + st * STG;
        #pragma unroll
        for (int it = 0; it < 2; it++) {
            int row = it ? r1a : r0a, s = it ? s1a : s0a;
            __half2 h0 = __floats2half2_rn(r[it].x, r[it].y);
            __half2 h1 = __floats2half2_rn(r[it].z, r[it].w);
            uint2 uu;
            uu.x = *reinterpret_cast<unsigned*>(&h0);
            uu.y = *reinterpret_cast<unsigned*>(&h1);
            *(uint2*)(base + A16OFF + row * 80 + s * 8) = uu;
        }
    };

    float c[2][4][4];
    #pragma unroll
    for (int i = 0; i < 2; i++)
        #pragma unroll
        for (int j = 0; j < 4; j++)
            c[i][j][0] = c[i][j][1] = c[i][j][2] = c[i][j][3] = 0.f;

    float4 ra0[2], ra1[2];
    loadB(0, 0); loadB(1, 1); loadB(2, 2);
    ldgA(0, ra0); ldgA(1, ra1);
    cvtsts(0, ra0);                         // A(0) -> stage 0

    for (int ch = 0; ch < 512; ch++) {
        asm volatile("cp.async.wait_group 2;" ::: "memory");  // B(ch) resident
        __syncthreads();                    // publish A16(ch) + B16(ch); free stage (ch-1)&3
        if (ch + 3 < 512) loadB(ch + 3, (ch + 3) & 3);
        else asm volatile("cp.async.commit_group;" ::: "memory");
        if ((ch & 1) == 0) {
            if (ch + 2 < 512) ldgA(ch + 2, ra0);
            if (ch + 1 < 512) cvtsts((ch + 1) & 3, ra1);      // A(ch+1)
        } else {
            if (ch + 2 < 512) ldgA(ch + 2, ra1);
            if (ch + 1 < 512) cvtsts((ch + 1) & 3, ra0);
        }

        const uint32_t sbu = smb + (ch & 3) * STG;
        #pragma unroll
        for (int ks = 0; ks < 2; ks++) {
            uint32_t a[2][4], b[4][2];
            #pragma unroll
            for (int i = 0; i < 2; i++)
                LDSM4(a[i][0], a[i][1], a[i][2], a[i][3], sbu + aoff + i * 1280u + ks * 32u);
            #pragma unroll
            for (int jp = 0; jp < 2; jp++)
                LDSM4(b[2*jp][0], b[2*jp][1], b[2*jp+1][0], b[2*jp+1][1],
                      sbu + boff + jp * 1280u + ks * 32u);
            #pragma unroll
            for (int i = 0; i < 2; i++)
                #pragma unroll
                for (int j = 0; j < 4; j++)
                    asm volatile(
                        "mma.sync.aligned.m16n8k16.row.col.f32.f16.f16.f32 "
                        "{%0,%1,%2,%3}, {%4,%5,%6,%7}, {%8,%9}, {%0,%1,%2,%3};"
                        : "+f"(c[i][j][0]), "+f"(c[i][j][1]),
                          "+f"(c[i][j][2]), "+f"(c[i][j][3])
                        : "r"(a[i][0]), "r"(a[i][1]), "r"(a[i][2]), "r"(a[i][3]),
                          "r"(b[j][0]), "r"(b[j][1]));
        }
    }

    // epilogue 1: accumulators -> g_H
    #pragma unroll
    for (int i = 0; i < 2; i++)
        #pragma unroll
        for (int j = 0; j < 4; j++) {
            int row = m0 + wm + i * 16 + gid;
            int col = wn + j * 8 + tig * 2;
            *(float2*)&g_H[(size_t)row * 128 + col]       = make_float2(c[i][j][0], c[i][j][1]);
            *(float2*)&g_H[(size_t)(row + 8) * 128 + col] = make_float2(c[i][j][2], c[i][j][3]);
        }

    // epilogue 2: fused per-CTA column sums / sumsq (deterministic)
    float* sred = (float*)smc;          // [4][128]
    float* qred = sred + 512;           // [4][128]
    __syncthreads();
    #pragma unroll
    for (int j = 0; j < 4; j++) {
        float s0 = 0.f, s1 = 0.f, q0 = 0.f, q1 = 0.f;
        #pragma unroll
        for (int i = 0; i < 2; i++) {
            s0 += c[i][j][0] + c[i][j][2];
            s1 += c[i][j][1] + c[i][j][3];
            q0 += c[i][j][0] * c[i][j][0] + c[i][j][2] * c[i][j][2];
            q1 += c[i][j][1] * c[i][j][1] + c[i][j][3] * c[i][j][3];
        }
        #pragma unroll
        for (int m = 4; m <= 16; m <<= 1) {
            s0 += __shfl_xor_sync(0xffffffffu, s0, m);
            s1 += __shfl_xor_sync(0xffffffffu, s1, m);
            q0 += __shfl_xor_sync(0xffffffffu, q0, m);
            q1 += __shfl_xor_sync(0xffffffffu, q1, m);
        }
        if (gid == 0) {
            int col = wn + j * 8 + tig * 2;
            int band = wid & 3;
            sred[band * 128 + col]     = s0;
            sred[band * 128 + col + 1] = s1;
            qred[band * 128 + col]     = q0;
            qred[band * 128 + col + 1] = q1;
        }
    }
    __syncthreads();
    if (tid < 128) {
        g_ps[blockIdx.x * 128 + tid] =
            sred[tid] + sred[128 + tid] + sred[256 + tid] + sred[384 + tid];
        g_pq[blockIdx.x * 128 + tid] =
            qred[tid] + qred[128 + tid] + qred[256 + tid] + qred[384 + tid];
    }
}

// ---------------- k_fin: mean / scale ----------------
__global__ void k_fin(const float* __restrict__ gamma, const float* __restrict__ beta) {
    __shared__ float ss[8][128], qq[8][128];
    int t = threadIdx.x, j = t & 127, g = t >> 7;
    float s = 0.f, q = 0.f;
    #pragma unroll
    for (int b = g * 16; b < g * 16 + 16; b++) { s += g_ps[b * 128 + j]; q += g_pq[b * 128 + j]; }
    ss[g][j] = s; qq[g][j] = q;
    __syncthreads();
    if (t < 128) {
        float S = 0.f, Q = 0.f;
        #pragma unroll
        for (int g2 = 0; g2 < 8; g2++) { S += ss[g2][t]; Q += qq[g2][t]; }
        float m = S * (1.f / NR);
        float var = Q * (1.f / NR) - m * m;
        g_mean[t] = m;
        g_scale[t] = gamma[t] * rsqrtf(var + 1e-5f);
        g_beta2[t] = beta[t];
    }
}

// ---------------- k_apply: BN + LeakyReLU ----------------
__global__ void k_apply(float* __restrict__ out) {
    size_t i = (size_t)blockIdx.x * blockDim.x + threadIdx.x;
    int c = ((int)(i & 31)) * 4;
    float4 h = ((const float4*)g_H)[i];
    float4 r; float t;
    t = (h.x - g_mean[c+0]) * g_scale[c+0] + g_beta2[c+0]; r.x = t >= 0.f ? t : 0.2f * t;
    t = (h.y - g_mean[c+1]) * g_scale[c+1] + g_beta2[c+1]; r.y = t >= 0.f ? t : 0.2f * t;
    t = (h.z - g_mean[c+2]) * g_scale[c+2] + g_beta2[c+2]; r.z = t >= 0.f ? t : 0.2f * t;
    t = (h.w - g_mean[c+3]) * g_scale[c+3] + g_beta2[c+3]; r.w = t >= 0.f ? t : 0.2f * t;
    ((float4*)out)[i] = r;
}

extern "C" void kernel_launch(void* const* d_in, const int* in_sizes, int n_in,
                              void* d_out, int out_size) {
    const float* x     = (const float*)d_in[0];
    const float* A     = (const float*)d_in[1];
    const float* W     = (const float*)d_in[2];
    // d_in[3] = bias b: cancels exactly under BatchNorm -> unused
    const float* gamma = (const float*)d_in[4];
    const float* beta  = (const float*)d_in[5];
    float* out = (float*)d_out;

    cudaFuncSetAttribute(k_xw,   cudaFuncAttributeMaxDynamicSharedMemorySize, 82944);
    cudaFuncSetAttribute(k_gemm, cudaFuncAttributeMaxDynamicSharedMemorySize, 4 * STG);

    k_xw   <<<512, 128, 82944>>>(x, W);
    k_gemm <<<128, 512, 4 * STG>>>(A);
    k_fin  <<<1, 1024>>>(gamma, beta);
    k_apply<<<2048, 256>>>(out);
}

// round 16
// speedup vs baseline: 1.2164x; 1.2164x over previous
#include <cuda_runtime.h>
#include <cuda_fp16.h>
#include <cstdint>

#define NR 16384
// per-stage smem layout (bytes)
#define A32OFF 0            // 128 rows x 144B (32 fp32 + 16B pad)
#define B16OFF 18432        // 128 rows x 80B  (32 fp16 + 16B pad)
#define A16OFF 28672        // 128 rows x 80B
#define STGB   38912
#define NCTA   148
#define TOTCH  65536        // 128 tiles * 512 K-chunks

__device__ __half g_Th[(size_t)128 * NR];       // Tt[j][r] = fp16((X@W)[r][j]), K-major
__device__ float  g_Hp[3ull * NR * 128];        // split-K partial planes
__device__ float  g_H[(size_t)NR * 128];        // final H
__device__ float  g_ps[512 * 128], g_pq[512 * 128];
__device__ float  g_mean[128], g_scale[128], g_beta2[128];

__device__ __forceinline__ uint32_t s2u(const void* p) {
    uint32_t a;
    asm("{ .reg .u64 t; cvta.to.shared.u64 t, %1; cvt.u32.u64 %0, t; }" : "=r"(a) : "l"(p));
    return a;
}
#define LDSM4(r0, r1, r2, r3, addr) \
    asm volatile("ldmatrix.sync.aligned.m8n8.x4.shared.b16 {%0,%1,%2,%3}, [%4];" \
                 : "=r"(r0), "=r"(r1), "=r"(r2), "=r"(r3) : "r"(addr))

// staircase geometry: CTA r owns global chunks [seg_start(r), seg_start(r+1))
__device__ __forceinline__ int seg_start(int r) {
    return (int)(((long long)r << 16) / NCTA);
}
__device__ __forceinline__ int tile_r0(int t) {          // first CTA covering tile t
    int r = (int)(((long long)t * 512 * NCTA) >> 16);
    while (r > 0 && seg_start(r) > 512 * t) r--;
    while (seg_start(r + 1) <= 512 * t) r++;
    return r;
}

// ---------------- k1: Tt = fp16((X @ W)^T) ----------------
__global__ void k_xw(const float* __restrict__ X, const float* __restrict__ W) {
    extern __shared__ float sm[];
    float* ws = sm;              // [128*128] W
    float* xs = sm + 16384;      // [128]
    float* tl = sm + 16512;      // [128*33]
    int j = threadIdx.x;
    for (int i = j; i < 16384; i += 128) ws[i] = W[i];
    int r0 = blockIdx.x * 32;
    __syncthreads();
    for (int rr = 0; rr < 32; rr++) {
        xs[j] = X[(size_t)(r0 + rr) * 128 + j];
        __syncthreads();
        float acc = 0.f;
        #pragma unroll 16
        for (int k = 0; k < 128; k++) acc += xs[k] * ws[k * 128 + j];
        tl[j * 33 + rr] = acc;
        __syncthreads();
    }
    for (int idx = j; idx < 4096; idx += 128) {
        int jj = idx >> 5, r2 = idx & 31;
        g_Th[(size_t)jj * NR + r0 + r2] = __float2half_rn(tl[jj * 33 + r2]);
    }
}

// ---------------- k2: staircase split-K fp16 mma.sync GEMM ----------------
__global__ void __launch_bounds__(256, 1) k_gemm(const float* __restrict__ A) {
    extern __shared__ __align__(16) char smc[];
    const int tid = threadIdx.x, wid = tid >> 5, lid = tid & 31;
    const int gid = lid >> 2, tig = lid & 3;
    const int wm = (wid & 1) * 64;      // warps 2(M) x 4(N), warp tile 64x32
    const int wn = (wid >> 1) * 32;
    const uint32_t smb = s2u(smc);
    const int bid = blockIdx.x;
    const int s = seg_start(bid), e = seg_start(bid + 1);

    const uint32_t aoff = A16OFF + (uint32_t)(wm + (lid & 15)) * 80u + ((lid >> 4) * 16u);
    const uint32_t boff = B16OFF + (uint32_t)(wn + ((lid & 16) >> 1) + (lid & 7)) * 80u
                        + ((lid & 8) ? 16u : 0u);

    // load global chunk c into stage st (per thread: 4 A-segs + 2 B-segs, 16B each)
    auto load = [&](int c, int st) {
        uint32_t base = smb + (uint32_t)st * STGB;
        const int m0 = (c >> 9) * 128, kc = (c & 511) * 32;
        #pragma unroll
        for (int it = 0; it < 4; it++) {          // A: 1024 x 16B fp32
            int u = tid + it * 256, row = u >> 3, sg = u & 7;
            uint32_t dst = base + A32OFF + row * 144 + sg * 16;
            const float* gp = A + (size_t)(m0 + row) * NR + kc + sg * 4;
            asm volatile("cp.async.cg.shared.global [%0], [%1], 16;" :: "r"(dst), "l"(gp));
        }
        #pragma unroll
        for (int it = 0; it < 2; it++) {          // B: 512 x 16B fp16
            int v = tid + it * 256, n = v >> 2, sg = v & 3;
            uint32_t dst = base + B16OFF + n * 80 + sg * 16;
            const __half* gp = g_Th + (size_t)n * NR + kc + sg * 8;
            asm volatile("cp.async.cg.shared.global [%0], [%1], 16;" :: "r"(dst), "l"(gp));
        }
        asm volatile("cp.async.commit_group;" ::: "memory");
    };
    // each thread converts exactly the A-segments IT loaded (wait_group-only visibility)
    auto convertA = [&](int c) {
        char* base = smc + (c & 3) * STGB;
        #pragma unroll
        for (int it = 0; it < 4; it++) {
            int u = tid + it * 256, row = u >> 3, sg = u & 7;
            float4 f = *(const float4*)(base + A32OFF + row * 144 + sg * 16);
            __half2 h0 = __floats2half2_rn(f.x, f.y);
            __half2 h1 = __floats2half2_rn(f.z, f.w);
            uint2 uu;
            uu.x = *reinterpret_cast<unsigned*>(&h0);
            uu.y = *reinterpret_cast<unsigned*>(&h1);
            *(uint2*)(base + A16OFF + row * 80 + sg * 8) = uu;
        }
    };

    float c[4][4][4];
    auto zeroacc = [&]() {
        #pragma unroll
        for (int i = 0; i < 4; i++)
            #pragma unroll
            for (int j = 0; j < 4; j++)
                c[i][j][0] = c[i][j][1] = c[i][j][2] = c[i][j][3] = 0.f;
    };
    zeroacc();

    load(s, s & 3); load(s + 1, (s + 1) & 3); load(s + 2, (s + 2) & 3);
    asm volatile("cp.async.wait_group 2;" ::: "memory");
    convertA(s);

    for (int ch = s; ch < e; ch++) {
        __syncthreads();   // publishes convertA(ch) + B16(ch); frees stage (ch-1)&3
        if (ch + 3 < e) load(ch + 3, (ch + 3) & 3);
        else asm volatile("cp.async.commit_group;" ::: "memory");
        asm volatile("cp.async.wait_group 2;" ::: "memory");
        if (ch + 1 < e) convertA(ch + 1);

        const uint32_t sbu = smb + (ch & 3) * STGB;
        #pragma unroll
        for (int ks = 0; ks < 2; ks++) {
            uint32_t a[4][4], b[4][2];
            #pragma unroll
            for (int i = 0; i < 4; i++)
                LDSM4(a[i][0], a[i][1], a[i][2], a[i][3], sbu + aoff + i * 1280u + ks * 32u);
            #pragma unroll
            for (int jp = 0; jp < 2; jp++)
                LDSM4(b[2*jp][0], b[2*jp][1], b[2*jp+1][0], b[2*jp+1][1],
                      sbu + boff + jp * 1280u + ks * 32u);
            #pragma unroll
            for (int i = 0; i < 4; i++)
                #pragma unroll
                for (int j = 0; j < 4; j++)
                    asm volatile(
                        "mma.sync.aligned.m16n8k16.row.col.f32.f16.f16.f32 "
                        "{%0,%1,%2,%3}, {%4,%5,%6,%7}, {%8,%9}, {%0,%1,%2,%3};"
                        : "+f"(c[i][j][0]), "+f"(c[i][j][1]),
                          "+f"(c[i][j][2]), "+f"(c[i][j][3])
                        : "r"(a[i][0]), "r"(a[i][1]), "r"(a[i][2]), "r"(a[i][3]),
                          "r"(b[j][0]), "r"(b[j][1]));
        }

        // flush at tile boundary or end of this CTA's range
        if (((ch + 1) & 511) == 0 || ch == e - 1) {
            int t = ch >> 9;
            int p = bid - tile_r0(t);                       // plane 0..2, disjoint slots
            float* dst = g_Hp + ((size_t)p * NR + (size_t)t * 128) * 128;
            #pragma unroll
            for (int i = 0; i < 4; i++)
                #pragma unroll
                for (int j = 0; j < 4; j++) {
                    int row = wm + i * 16 + gid;
                    int col = wn + j * 8 + tig * 2;
                    *(float2*)&dst[(size_t)row * 128 + col] =
                        make_float2(c[i][j][0], c[i][j][1]);
                    *(float2*)&dst[(size_t)(row + 8) * 128 + col] =
                        make_float2(c[i][j][2], c[i][j][3]);
                }
            zeroacc();
        }
    }
    asm volatile("cp.async.wait_all;" ::: "memory");
}

// ---------------- k_red: sum planes -> g_H, per-block column stats ----------------
__global__ void __launch_bounds__(256) k_red() {
    __shared__ float sred[8][128], qred[8][128];
    const int b = blockIdx.x;                 // 512 blocks
    const int t = b >> 2, band = (b & 3) * 32;
    const int tid = threadIdx.x, lid = tid & 31, w = tid >> 5;
    const int r0 = tile_r0(t);
    int nseg = 1;
    while (r0 + nseg < NCTA && seg_start(r0 + nseg) < 512 * (t + 1)) nseg++;

    const int rloc = band + (tid >> 3);                    // row within tile
    const size_t grow = ((size_t)t * 128 + rloc) * 128;
    float sacc[4][4], qacc[4][4];
    #pragma unroll
    for (int j = 0; j < 4; j++) {
        const int cs = (tid & 7) + 8 * j;                  // float4 column segment
        float4 h = *(const float4*)&g_Hp[grow + cs * 4];
        if (nseg > 1) {
            float4 h1 = *(const float4*)&g_Hp[(size_t)NR * 128 + grow + cs * 4];
            h.x += h1.x; h.y += h1.y; h.z += h1.z; h.w += h1.w;
        }
        if (nseg > 2) {
            float4 h2 = *(const float4*)&g_Hp[2ull * NR * 128 + grow + cs * 4];
            h.x += h2.x; h.y += h2.y; h.z += h2.z; h.w += h2.w;
        }
        *(float4*)&g_H[grow + cs * 4] = h;
        sacc[j][0] = h.x; sacc[j][1] = h.y; sacc[j][2] = h.z; sacc[j][3] = h.w;
        qacc[j][0] = h.x * h.x; qacc[j][1] = h.y * h.y;
        qacc[j][2] = h.z * h.z; qacc[j][3] = h.w * h.w;
    }
    // reduce over the 4 rows held by this warp (lanes differing in bits 3,4)
    #pragma unroll
    for (int j = 0; j < 4; j++)
        #pragma unroll
        for (int k = 0; k < 4; k++) {
            sacc[j][k] += __shfl_xor_sync(0xffffffffu, sacc[j][k], 8);
            sacc[j][k] += __shfl_xor_sync(0xffffffffu, sacc[j][k], 16);
            qacc[j][k] += __shfl_xor_sync(0xffffffffu, qacc[j][k], 8);
            qacc[j][k] += __shfl_xor_sync(0xffffffffu, qacc[j][k], 16);
        }
    if (lid < 8) {
        #pragma unroll
        for (int j = 0; j < 4; j++) {
            int cb = (lid + 8 * j) * 4;
            #pragma unroll
            for (int k = 0; k < 4; k++) { sred[w][cb + k] = sacc[j][k]; qred[w][cb + k] = qacc[j][k]; }
        }
    }
    __syncthreads();
    if (tid < 128) {
        float S = 0.f, Q = 0.f;
        #pragma unroll
        for (int w2 = 0; w2 < 8; w2++) { S += sred[w2][tid]; Q += qred[w2][tid]; }
        g_ps[b * 128 + tid] = S;
        g_pq[b * 128 + tid] = Q;
    }
}

// ---------------- k_fin: mean / scale ----------------
__global__ void k_fin(const float* __restrict__ gamma, const float* __restrict__ beta) {
    __shared__ float ss[8][128], qq[8][128];
    int t = threadIdx.x, j = t & 127, g = t >> 7;
    float s = 0.f, q = 0.f;
    #pragma unroll 8
    for (int b = g * 64; b < g * 64 + 64; b++) { s += g_ps[b * 128 + j]; q += g_pq[b * 128 + j]; }
    ss[g][j] = s; qq[g][j] = q;
    __syncthreads();
    if (t < 128) {
        float S = 0.f, Q = 0.f;
        #pragma unroll
        for (int g2 = 0; g2 < 8; g2++) { S += ss[g2][t]; Q += qq[g2][t]; }
        float m = S * (1.f / NR);
        float var = Q * (1.f / NR) - m * m;
        g_mean[t] = m;
        g_scale[t] = gamma[t] * rsqrtf(var + 1e-5f);
        g_beta2[t] = beta[t];
    }
}

// ---------------- k_apply: BN + LeakyReLU ----------------
__global__ void k_apply(float* __restrict__ out) {
    size_t i = (size_t)blockIdx.x * blockDim.x + threadIdx.x;   // float4 units
    int c = ((int)(i & 31)) * 4;
    float4 h = ((const float4*)g_H)[i];
    float4 r; float t;
    t = (h.x - g_mean[c+0]) * g_scale[c+0] + g_beta2[c+0]; r.x = t >= 0.f ? t : 0.2f * t;
    t = (h.y - g_mean[c+1]) * g_scale[c+1] + g_beta2[c+1]; r.y = t >= 0.f ? t : 0.2f * t;
    t = (h.z - g_mean[c+2]) * g_scale[c+2] + g_beta2[c+2]; r.z = t >= 0.f ? t : 0.2f * t;
    t = (h.w - g_mean[c+3]) * g_scale[c+3] + g_beta2[c+3]; r.w = t >= 0.f ? t : 0.2f * t;
    ((float4*)out)[i] = r;
}

extern "C" void kernel_launch(void* const* d_in, const int* in_sizes, int n_in,
                              void* d_out, int out_size) {
    const float* x     = (const float*)d_in[0];
    const float* A     = (const float*)d_in[1];
    const float* W     = (const float*)d_in[2];
    // d_in[3] = bias b: per-column constant, cancels exactly under BatchNorm -> unused
    const float* gamma = (const float*)d_in[4];
    const float* beta  = (const float*)d_in[5];
    float* out = (float*)d_out;

    cudaFuncSetAttribute(k_xw,   cudaFuncAttributeMaxDynamicSharedMemorySize, 82944);
    cudaFuncSetAttribute(k_gemm, cudaFuncAttributeMaxDynamicSharedMemorySize, 4 * STGB);

    k_xw   <<<512, 128, 82944>>>(x, W);
    k_gemm <<<NCTA, 256, 4 * STGB>>>(A);
    k_red  <<<512, 256>>>();
    k_fin  <<<1, 1024>>>(gamma, beta);
    k_apply<<<2048, 256>>>(out);
}